// round 13
// baseline (speedup 1.0000x reference)
#include <cuda_runtime.h>
#include <cuda_bf16.h>
#include <math.h>
#include <stdint.h>

#define T_TOK 1024
#define H_DIM 1024
#define E_NUM 8
#define I_DIM 1024
#define ALPHA 1.702f
#define LIMIT 7.0f
#define BK 16
#define STR 24   // smem row stride (elems); conflict-free for STS.128 and ldmatrix

// ---------------- scratch ----------------------------------------------------
__device__ int   g_top_idx[T_TOK * 2];
__device__ float g_top_w[T_TOK * 2];
__device__ int   g_cnt[E_NUM];
__device__ int   g_tok[E_NUM][T_TOK];
__device__ float g_wt[E_NUM][T_TOK];
__device__ __align__(256) float g_act[(size_t)E_NUM * T_TOK * I_DIM];  // 32 MiB

// ---------------- mma.sync / ldmatrix / split helpers ------------------------
__device__ __forceinline__ void mma16816(float c[4], const uint32_t a[4],
                                         const uint32_t b[2]) {
    asm volatile(
        "mma.sync.aligned.m16n8k16.row.col.f32.bf16.bf16.f32 "
        "{%0,%1,%2,%3}, {%4,%5,%6,%7}, {%8,%9}, {%0,%1,%2,%3};"
        : "+f"(c[0]), "+f"(c[1]), "+f"(c[2]), "+f"(c[3])
        : "r"(a[0]), "r"(a[1]), "r"(a[2]), "r"(a[3]), "r"(b[0]), "r"(b[1]));
}
__device__ __forceinline__ void ldsm4(uint32_t f[4], uint32_t addr) {
    asm volatile(
        "ldmatrix.sync.aligned.m8n8.x4.shared.b16 {%0,%1,%2,%3}, [%4];"
        : "=r"(f[0]), "=r"(f[1]), "=r"(f[2]), "=r"(f[3]) : "r"(addr));
}
__device__ __forceinline__ uint32_t bfpack(__nv_bfloat16 a, __nv_bfloat16 b) {
    __nv_bfloat162 t = __halves2bfloat162(a, b);
    return *reinterpret_cast<uint32_t*>(&t);
}
__device__ __forceinline__ void split2(float f0, float f1,
                                       uint32_t& hi, uint32_t& lo) {
    __nv_bfloat16 h0 = __float2bfloat16(f0);
    __nv_bfloat16 h1 = __float2bfloat16(f1);
    hi = bfpack(h0, h1);
    lo = bfpack(__float2bfloat16(f0 - __bfloat162float(h0)),
                __float2bfloat16(f1 - __bfloat162float(h1)));
}
// ldmatrix lane->element offsets (16x16 tiles)
__device__ __forceinline__ int aoff_lane(int lane) {
    return ((lane & 7) + ((lane >> 3) & 1) * 8) * STR + ((lane >> 4) & 1) * 8;
}
__device__ __forceinline__ int boff_lane(int lane) {
    return (lane & 7) * STR + ((lane >> 3) & 1) * 8 + ((lane >> 4) & 1) * 8 * STR;
}

// ---------------- router (proven) --------------------------------------------
__global__ void router_k(const float* __restrict__ x,
                         const float* __restrict__ Wr,
                         const float* __restrict__ br) {
    int t = blockIdx.x;
    int lane = threadIdx.x & 31;
    int warp = threadIdx.x >> 5;
    const float* xr = x + (size_t)t * H_DIM;
    const float* wr = Wr + (size_t)warp * H_DIM;
    float s = 0.f;
#pragma unroll
    for (int h = lane * 4; h < H_DIM; h += 128) {
        float4 a = *(const float4*)(xr + h);
        float4 b = *(const float4*)(wr + h);
        s += a.x * b.x + a.y * b.y + a.z * b.z + a.w * b.w;
    }
#pragma unroll
    for (int o = 16; o; o >>= 1) s += __shfl_xor_sync(0xffffffffu, s, o);
    __shared__ float lg[E_NUM];
    if (lane == 0) lg[warp] = s + br[warp];
    __syncthreads();
    if (threadIdx.x == 0) {
        float mx = lg[0];
#pragma unroll
        for (int e = 1; e < E_NUM; e++) mx = fmaxf(mx, lg[e]);
        float ex[E_NUM], sum = 0.f;
#pragma unroll
        for (int e = 0; e < E_NUM; e++) { ex[e] = expf(lg[e] - mx); sum += ex[e]; }
        int i0 = 0;
#pragma unroll
        for (int e = 1; e < E_NUM; e++) if (lg[e] > lg[i0]) i0 = e;
        int i1 = (i0 == 0) ? 1 : 0;
#pragma unroll
        for (int e = 0; e < E_NUM; e++) if (e != i0 && lg[e] > lg[i1]) i1 = e;
        float inv = 1.f / sum;
        g_top_idx[2 * t + 0] = i0;  g_top_idx[2 * t + 1] = i1;
        g_top_w[2 * t + 0] = ex[i0] * inv;  g_top_w[2 * t + 1] = ex[i1] * inv;
    }
}

// ---------------- dispatch (serial, proven) ----------------------------------
__global__ void dispatch_k() {
    int e = threadIdx.x;
    if (e >= E_NUM) return;
    int c = 0;
    for (int t = 0; t < T_TOK; t++) {
        int i0 = g_top_idx[2 * t + 0];
        int i1 = g_top_idx[2 * t + 1];
        if (i0 == e)      { g_tok[e][c] = t; g_wt[e][c] = g_top_w[2 * t + 0]; c++; }
        else if (i1 == e) { g_tok[e][c] = t; g_wt[e][c] = g_top_w[2 * t + 1]; c++; }
    }
    g_cnt[e] = c;
}

// ---------------- GEMM1 (mma): act = GLU(x_e @ W1_e + b1_e) ------------------
// CTA tile: 128 tokens x (64 gate + paired 64 up), BK=16, 2-stage smem ring.
// Warps 4(m) x 2(n); warp tile 32m x (32 gate + 32 up).
__global__ void __launch_bounds__(256, 2) gemm1_mma(const float* __restrict__ x,
                                                    const float* __restrict__ W1,
                                                    const float* __restrict__ b1) {
    int e = blockIdx.z;
    int cnt = g_cnt[e];
    int mB = blockIdx.y * 128;
    if (mB >= cnt) return;
    int nB = blockIdx.x * 64;

    __shared__ __align__(16) __nv_bfloat16 sAh[2][128 * STR];
    __shared__ __align__(16) __nv_bfloat16 sAl[2][128 * STR];
    __shared__ __align__(16) __nv_bfloat16 sBh[2][128 * STR];  // 64 gate + 64 up
    __shared__ __align__(16) __nv_bfloat16 sBl[2][128 * STR];

    int tid = threadIdx.x, lane = tid & 31, wid = tid >> 5;
    int wm = wid >> 1, wn = wid & 1, g = lane >> 2, tig = lane & 3;

    const float* W1e = W1 + (size_t)e * H_DIM * 2 * I_DIM;
    // A: thread -> (row, 8 cols); token row from gmem dispatch table
    int arow = tid >> 1, acol = (tid & 1) * 8;
    int t_row = (mB + arow < cnt) ? g_tok[e][mB + arow] : -1;
    const float* aptr = x + (size_t)(t_row >= 0 ? t_row : 0) * H_DIM + acol;
    // B: thread -> (column n, 8 k-rows); n<64 gate col nB+n, n>=64 up col
    int bn = tid & 127, bkh = (tid >> 7) * 8;
    const float* bcol = W1e + (bn < 64 ? nB + bn : I_DIM + nB + (bn - 64));

    uint32_t uAh = (uint32_t)__cvta_generic_to_shared(sAh);
    uint32_t uAl = (uint32_t)__cvta_generic_to_shared(sAl);
    uint32_t uBh = (uint32_t)__cvta_generic_to_shared(sBh);
    uint32_t uBl = (uint32_t)__cvta_generic_to_shared(sBl);
    const uint32_t STG = 128 * STR * 2;   // bytes per stage
    int aoff = aoff_lane(lane), boff = boff_lane(lane);

    float aReg[8], bReg[8];
    float acc[2][8][4];
#pragma unroll
    for (int a_ = 0; a_ < 2; a_++)
#pragma unroll
        for (int b_ = 0; b_ < 8; b_++)
#pragma unroll
            for (int k_ = 0; k_ < 4; k_++) acc[a_][b_][k_] = 0.f;

#define G1_LOAD(c) do {                                                         \
        int k0 = (c) * BK;                                                      \
        if (t_row >= 0) {                                                       \
            float4 v0 = *(const float4*)(aptr + k0);                            \
            float4 v1 = *(const float4*)(aptr + k0 + 4);                        \
            aReg[0] = v0.x; aReg[1] = v0.y; aReg[2] = v0.z; aReg[3] = v0.w;     \
            aReg[4] = v1.x; aReg[5] = v1.y; aReg[6] = v1.z; aReg[7] = v1.w;     \
        } else {                                                                \
            _Pragma("unroll") for (int i = 0; i < 8; i++) aReg[i] = 0.f;        \
        }                                                                       \
        _Pragma("unroll")                                                       \
        for (int k = 0; k < 8; k++)                                             \
            bReg[k] = bcol[(size_t)(k0 + bkh + k) * (2 * I_DIM)];               \
    } while (0)

    G1_LOAD(0);
    for (int c = 0; c < H_DIM / BK; c++) {
        int buf = c & 1;
        {
            uint32_t ha[4], la[4];
#pragma unroll
            for (int k = 0; k < 4; k++)
                split2(aReg[2 * k], aReg[2 * k + 1], ha[k], la[k]);
            *(uint4*)&sAh[buf][arow * STR + acol] = make_uint4(ha[0], ha[1], ha[2], ha[3]);
            *(uint4*)&sAl[buf][arow * STR + acol] = make_uint4(la[0], la[1], la[2], la[3]);
            uint32_t hb[4], lb[4];
#pragma unroll
            for (int k = 0; k < 4; k++)
                split2(bReg[2 * k], bReg[2 * k + 1], hb[k], lb[k]);
            *(uint4*)&sBh[buf][bn * STR + bkh] = make_uint4(hb[0], hb[1], hb[2], hb[3]);
            *(uint4*)&sBl[buf][bn * STR + bkh] = make_uint4(lb[0], lb[1], lb[2], lb[3]);
        }
        __syncthreads();
        if (c + 1 < H_DIM / BK) G1_LOAD(c + 1);
        {
            uint32_t bb = buf * STG;
            uint32_t ah[2][4], al[2][4];
#pragma unroll
            for (int mi = 0; mi < 2; mi++) {
                uint32_t ao = bb + (uint32_t)((wm * 32 + mi * 16) * STR + aoff) * 2;
                ldsm4(ah[mi], uAh + ao);
                ldsm4(al[mi], uAl + ao);
            }
            uint32_t bh[8][2], bl[8][2];
#pragma unroll
            for (int p = 0; p < 4; p++) {
                int nb = (p < 2) ? wn * 32 + p * 16
                                 : 64 + wn * 32 + (p - 2) * 16;
                uint32_t bo = bb + (uint32_t)(nb * STR + boff) * 2;
                uint32_t t4[4];
                ldsm4(t4, uBh + bo);
                bh[2 * p][0] = t4[0]; bh[2 * p][1] = t4[1];
                bh[2 * p + 1][0] = t4[2]; bh[2 * p + 1][1] = t4[3];
                ldsm4(t4, uBl + bo);
                bl[2 * p][0] = t4[0]; bl[2 * p][1] = t4[1];
                bl[2 * p + 1][0] = t4[2]; bl[2 * p + 1][1] = t4[3];
            }
#pragma unroll
            for (int ni = 0; ni < 8; ni++)
#pragma unroll
                for (int mi = 0; mi < 2; mi++) {
                    mma16816(acc[mi][ni], ah[mi], bh[ni]);
                    mma16816(acc[mi][ni], al[mi], bh[ni]);
                    mma16816(acc[mi][ni], ah[mi], bl[ni]);
                }
        }
    }

    // fused GLU epilogue -> fp32 act
#pragma unroll
    for (int mi = 0; mi < 2; mi++) {
        int m0 = mB + wm * 32 + mi * 16 + g;
#pragma unroll
        for (int ni = 0; ni < 4; ni++) {
            int j = nB + wn * 32 + ni * 8 + tig * 2;
            float bg0 = b1[(size_t)e * 2 * I_DIM + j];
            float bg1 = b1[(size_t)e * 2 * I_DIM + j + 1];
            float bu0 = b1[(size_t)e * 2 * I_DIM + I_DIM + j];
            float bu1 = b1[(size_t)e * 2 * I_DIM + I_DIM + j + 1];
#pragma unroll
            for (int h = 0; h < 2; h++) {
                int m = m0 + h * 8;
                if (m >= cnt) continue;
                float gv0 = acc[mi][ni][h * 2 + 0] + bg0;
                float gv1 = acc[mi][ni][h * 2 + 1] + bg1;
                float uv0 = acc[mi][ni + 4][h * 2 + 0] + bu0;
                float uv1 = acc[mi][ni + 4][h * 2 + 1] + bu1;
                gv0 = fminf(gv0, LIMIT);
                gv1 = fminf(gv1, LIMIT);
                uv0 = fminf(fmaxf(uv0, -LIMIT), LIMIT);
                uv1 = fminf(fmaxf(uv1, -LIMIT), LIMIT);
                float a0 = (uv0 + 1.f) * (gv0 / (1.f + __expf(-ALPHA * gv0)));
                float a1 = (uv1 + 1.f) * (gv1 / (1.f + __expf(-ALPHA * gv1)));
                float* ap = g_act + ((size_t)e * T_TOK + m) * I_DIM + j;
                ap[0] = a0;
                ap[1] = a1;
            }
        }
    }
}

// ---------------- GEMM2 (mma): out += w * (act @ W2_e + b2_e) ----------------
// CTA tile 128x128, BK=16, 2-stage smem ring; warps 2(m) x 4(n), tile 64x32.
__global__ void __launch_bounds__(256, 2) gemm2_mma(const float* __restrict__ W2,
                                                    const float* __restrict__ b2,
                                                    float* __restrict__ out) {
    int e = blockIdx.z;
    int cnt = g_cnt[e];
    int mB = blockIdx.y * 128;
    if (mB >= cnt) return;
    int nB = blockIdx.x * 128;

    __shared__ __align__(16) __nv_bfloat16 sAh[2][128 * STR];
    __shared__ __align__(16) __nv_bfloat16 sAl[2][128 * STR];
    __shared__ __align__(16) __nv_bfloat16 sBh[2][128 * STR];
    __shared__ __align__(16) __nv_bfloat16 sBl[2][128 * STR];

    int tid = threadIdx.x, lane = tid & 31, wid = tid >> 5;
    int wm = wid >> 2, wn = wid & 3, g = lane >> 2, tig = lane & 3;

    const float* W2e = W2 + (size_t)e * I_DIM * H_DIM;
    const float* Ae  = g_act + (size_t)e * T_TOK * I_DIM;
    int arow = tid >> 1, acol = (tid & 1) * 8;
    bool aok = (mB + arow) < cnt;
    const float* aptr = Ae + (size_t)(mB + arow) * I_DIM + acol;
    int bn = tid & 127, bkh = (tid >> 7) * 8;
    const float* bcol = W2e + nB + bn;

    uint32_t uAh = (uint32_t)__cvta_generic_to_shared(sAh);
    uint32_t uAl = (uint32_t)__cvta_generic_to_shared(sAl);
    uint32_t uBh = (uint32_t)__cvta_generic_to_shared(sBh);
    uint32_t uBl = (uint32_t)__cvta_generic_to_shared(sBl);
    const uint32_t STG = 128 * STR * 2;
    int aoff = aoff_lane(lane), boff = boff_lane(lane);

    float aReg[8], bReg[8];
    float acc[4][4][4];
#pragma unroll
    for (int a_ = 0; a_ < 4; a_++)
#pragma unroll
        for (int b_ = 0; b_ < 4; b_++)
#pragma unroll
            for (int k_ = 0; k_ < 4; k_++) acc[a_][b_][k_] = 0.f;

#define G2_LOAD(c) do {                                                         \
        int k0 = (c) * BK;                                                      \
        if (aok) {                                                              \
            float4 v0 = *(const float4*)(aptr + k0);                            \
            float4 v1 = *(const float4*)(aptr + k0 + 4);                        \
            aReg[0] = v0.x; aReg[1] = v0.y; aReg[2] = v0.z; aReg[3] = v0.w;     \
            aReg[4] = v1.x; aReg[5] = v1.y; aReg[6] = v1.z; aReg[7] = v1.w;     \
        } else {                                                                \
            _Pragma("unroll") for (int i = 0; i < 8; i++) aReg[i] = 0.f;        \
        }                                                                       \
        _Pragma("unroll")                                                       \
        for (int k = 0; k < 8; k++)                                             \
            bReg[k] = bcol[(size_t)(k0 + bkh + k) * H_DIM];                     \
    } while (0)

    G2_LOAD(0);
    for (int c = 0; c < I_DIM / BK; c++) {
        int buf = c & 1;
        {
            uint32_t ha[4], la[4];
#pragma unroll
            for (int k = 0; k < 4; k++)
                split2(aReg[2 * k], aReg[2 * k + 1], ha[k], la[k]);
            *(uint4*)&sAh[buf][arow * STR + acol] = make_uint4(ha[0], ha[1], ha[2], ha[3]);
            *(uint4*)&sAl[buf][arow * STR + acol] = make_uint4(la[0], la[1], la[2], la[3]);
            uint32_t hb[4], lb[4];
#pragma unroll
            for (int k = 0; k < 4; k++)
                split2(bReg[2 * k], bReg[2 * k + 1], hb[k], lb[k]);
            *(uint4*)&sBh[buf][bn * STR + bkh] = make_uint4(hb[0], hb[1], hb[2], hb[3]);
            *(uint4*)&sBl[buf][bn * STR + bkh] = make_uint4(lb[0], lb[1], lb[2], lb[3]);
        }
        __syncthreads();
        if (c + 1 < I_DIM / BK) G2_LOAD(c + 1);
        {
            uint32_t bb = buf * STG;
            uint32_t ah[4][4], al[4][4];
#pragma unroll
            for (int mi = 0; mi < 4; mi++) {
                uint32_t ao = bb + (uint32_t)((wm * 64 + mi * 16) * STR + aoff) * 2;
                ldsm4(ah[mi], uAh + ao);
                ldsm4(al[mi], uAl + ao);
            }
            uint32_t bh[4][2], bl[4][2];
#pragma unroll
            for (int p = 0; p < 2; p++) {
                uint32_t bo = bb + (uint32_t)((wn * 32 + p * 16) * STR + boff) * 2;
                uint32_t t4[4];
                ldsm4(t4, uBh + bo);
                bh[2 * p][0] = t4[0]; bh[2 * p][1] = t4[1];
                bh[2 * p + 1][0] = t4[2]; bh[2 * p + 1][1] = t4[3];
                ldsm4(t4, uBl + bo);
                bl[2 * p][0] = t4[0]; bl[2 * p][1] = t4[1];
                bl[2 * p + 1][0] = t4[2]; bl[2 * p + 1][1] = t4[3];
            }
#pragma unroll
            for (int mi = 0; mi < 4; mi++)
#pragma unroll
                for (int ni = 0; ni < 4; ni++) {
                    mma16816(acc[mi][ni], ah[mi], bh[ni]);
                    mma16816(acc[mi][ni], al[mi], bh[ni]);
                    mma16816(acc[mi][ni], ah[mi], bl[ni]);
                }
        }
    }

    // weighted combine epilogue (tok/wt straight from gmem)
#pragma unroll
    for (int mi = 0; mi < 4; mi++) {
        int mr0 = wm * 64 + mi * 16 + g;
#pragma unroll
        for (int h = 0; h < 2; h++) {
            int mr = mr0 + h * 8;
            int m = mB + mr;
            if (m >= cnt) continue;
            int t = g_tok[e][m];
            float w = g_wt[e][m];
            float* op = out + (size_t)t * H_DIM;
#pragma unroll
            for (int ni = 0; ni < 4; ni++) {
                int n = nB + wn * 32 + ni * 8 + tig * 2;
                float bb0 = b2[(size_t)e * H_DIM + n];
                float bb1 = b2[(size_t)e * H_DIM + n + 1];
                atomicAdd(op + n,     w * (acc[mi][ni][h * 2 + 0] + bb0));
                atomicAdd(op + n + 1, w * (acc[mi][ni][h * 2 + 1] + bb1));
            }
        }
    }
}

// ---------------- launcher ---------------------------------------------------
extern "C" void kernel_launch(void* const* d_in, const int* in_sizes, int n_in,
                              void* d_out, int out_size) {
    const float* x  = (const float*)d_in[0];
    const float* Wr = (const float*)d_in[1];
    const float* br = (const float*)d_in[2];
    const float* W1 = (const float*)d_in[3];
    const float* b1 = (const float*)d_in[4];
    const float* W2 = (const float*)d_in[5];
    const float* b2 = (const float*)d_in[6];
    float* out = (float*)d_out;

    cudaMemsetAsync(out, 0, (size_t)out_size * sizeof(float), 0);
    router_k<<<T_TOK, 256>>>(x, Wr, br);
    dispatch_k<<<1, 32>>>();
    gemm1_mma<<<dim3(I_DIM / 64, T_TOK / 128, E_NUM), 256>>>(x, W1, b1);
    gemm2_mma<<<dim3(H_DIM / 128, T_TOK / 128, E_NUM), 256>>>(W2, b2, out);
}